// round 1
// baseline (speedup 1.0000x reference)
#include <cuda_runtime.h>
#include <math.h>

#define B_ 4
#define T_ 2048
#define D_ 1024
#define H_ 16
#define P_ 64
#define M_ (B_*T_)   // 8192

// Scratch (allocation-free rule: __device__ globals)
__device__ float g_q[(size_t)B_*H_*T_*P_];
__device__ float g_k[(size_t)B_*H_*T_*P_];
__device__ float g_v[(size_t)B_*H_*T_*P_];
__device__ float g_y[(size_t)M_*D_];

// ---------------------------------------------------------------------------
// GEMM: C[M,1024] = A[M,1024] * W[1024,1024]
// MODE 0: A = x (param), blockIdx.z selects (Wq->g_q, Wk->g_k, Wv->g_v),
//         epilogue scatters to [B,H,T,P] layout.
// MODE 1: A = g_y (global), W = W0, C = C_plain (d_out), plain row-major.
// Tiles: 128x128x16, 256 threads, 8x8 per-thread microtile.
// ---------------------------------------------------------------------------
template <int MODE>
__global__ __launch_bounds__(256, 2)
void gemm_kernel(const float* __restrict__ A,
                 const float* __restrict__ W0,
                 const float* __restrict__ W1,
                 const float* __restrict__ W2,
                 float* __restrict__ C_plain)
{
    __shared__ float As[16][128];   // k-major (transposed A tile)
    __shared__ float Bs[16][128];

    const int K = 1024, N = 1024;
    const int m0 = blockIdx.y * 128;
    const int n0 = blockIdx.x * 128;

    const float* Ap;
    const float* W;
    float* Cq = nullptr;
    if (MODE == 0) {
        Ap = A;
        int z = blockIdx.z;
        W  = (z == 0) ? W0 : ((z == 1) ? W1 : W2);
        Cq = (z == 0) ? g_q : ((z == 1) ? g_k : g_v);
    } else {
        Ap = g_y;
        W  = W0;
    }

    const int tid = threadIdx.x;
    const int tx = tid & 15;
    const int ty = tid >> 4;

    float acc[8][8];
#pragma unroll
    for (int i = 0; i < 8; i++)
#pragma unroll
        for (int j = 0; j < 8; j++) acc[i][j] = 0.f;

    for (int kt = 0; kt < K; kt += 16) {
        // Load A tile (128x16) transposed into As[k][m], and B tile (16x128)
#pragma unroll
        for (int r = 0; r < 2; r++) {
            int idx = tid + r * 256;          // 0..511
            int arow = idx >> 2;              // 0..127
            int ac4  = (idx & 3) * 4;         // 0,4,8,12
            float4 av = *(const float4*)&Ap[(size_t)(m0 + arow) * K + kt + ac4];
            As[ac4 + 0][arow] = av.x;
            As[ac4 + 1][arow] = av.y;
            As[ac4 + 2][arow] = av.z;
            As[ac4 + 3][arow] = av.w;

            int brow = idx >> 5;              // 0..15
            int bc4  = (idx & 31) * 4;        // 0..124
            *(float4*)&Bs[brow][bc4] =
                *(const float4*)&W[(size_t)(kt + brow) * N + n0 + bc4];
        }
        __syncthreads();

#pragma unroll
        for (int k = 0; k < 16; k++) {
            float a[8], b[8];
            float4 a0 = *(const float4*)&As[k][ty * 8];
            float4 a1 = *(const float4*)&As[k][ty * 8 + 4];
            float4 b0 = *(const float4*)&Bs[k][tx * 8];
            float4 b1 = *(const float4*)&Bs[k][tx * 8 + 4];
            a[0]=a0.x; a[1]=a0.y; a[2]=a0.z; a[3]=a0.w;
            a[4]=a1.x; a[5]=a1.y; a[6]=a1.z; a[7]=a1.w;
            b[0]=b0.x; b[1]=b0.y; b[2]=b0.z; b[3]=b0.w;
            b[4]=b1.x; b[5]=b1.y; b[6]=b1.z; b[7]=b1.w;
#pragma unroll
            for (int i = 0; i < 8; i++)
#pragma unroll
                for (int j = 0; j < 8; j++)
                    acc[i][j] += a[i] * b[j];
        }
        __syncthreads();
    }

    // Epilogue
#pragma unroll
    for (int i = 0; i < 8; i++) {
        int mm = m0 + ty * 8 + i;
#pragma unroll
        for (int j4 = 0; j4 < 2; j4++) {
            int nn = n0 + tx * 8 + j4 * 4;
            float4 v = make_float4(acc[i][j4*4+0], acc[i][j4*4+1],
                                   acc[i][j4*4+2], acc[i][j4*4+3]);
            if (MODE == 0) {
                int b = mm >> 11;          // / 2048
                int t = mm & 2047;
                int h = nn >> 6;
                int p = nn & 63;
                size_t o = (((size_t)(b * H_ + h) * T_ + t) * P_ + p);
                *(float4*)&Cq[o] = v;
            } else {
                *(float4*)&C_plain[(size_t)mm * 1024 + nn] = v;
            }
        }
    }
}

// ---------------------------------------------------------------------------
// Flash attention, causal. Q/K/V in [B,H,T,P] layout (P=64).
// Block: 256 threads, 64 q-rows per block, 64-wide k tiles.
// Thread (tx,ty) 16x16 grid owns a 4x4 S microtile and 4x4 of O
// (rows ty*4.., cols tx*4..). Row softmax stats reduced via shfl over the
// 16-lane tx group.
// Output written to g_y in [B,T,H*P] layout for the final GEMM.
// ---------------------------------------------------------------------------
#define ATTN_SMEM_FLOATS (2*64*65 + 64*64)

__global__ __launch_bounds__(256, 2)
void attn_kernel()
{
    extern __shared__ float sm[];
    float* Qs = sm;               // [64][65] padded
    float* Ks = sm + 64*65;       // [64][65] padded, reused for P
    float* Vs = sm + 2*64*65;     // [64][64] unpadded (float4 aligned)

    const int bh = blockIdx.y;       // b*H + h
    const int b  = bh >> 4;
    const int h  = bh & 15;
    const int qt = blockIdx.x;
    const int q0 = qt * 64;

    const size_t base = (size_t)bh * T_ * P_;
    const float* Qp = g_q + base;
    const float* Kp = g_k + base;
    const float* Vp = g_v + base;

    const int tid = threadIdx.x;
    const int tx = tid & 15;
    const int ty = tid >> 4;

    // Load Q tile (64x64) into padded smem
    for (int it = tid; it < 64 * 16; it += 256) {
        int r  = it >> 4;
        int c4 = (it & 15) * 4;
        float4 v = *(const float4*)&Qp[(size_t)(q0 + r) * 64 + c4];
        Qs[r*65 + c4 + 0] = v.x;
        Qs[r*65 + c4 + 1] = v.y;
        Qs[r*65 + c4 + 2] = v.z;
        Qs[r*65 + c4 + 3] = v.w;
    }

    float acc[4][4];
    float m_i[4], l_i[4];
#pragma unroll
    for (int i = 0; i < 4; i++) {
        m_i[i] = -INFINITY;
        l_i[i] = 0.f;
#pragma unroll
        for (int j = 0; j < 4; j++) acc[i][j] = 0.f;
    }

    for (int jt = 0; jt <= qt; jt++) {
        const int j0 = jt * 64;
        __syncthreads();   // previous iter done with Ks(P)/Vs; Q load covered too
        for (int it = tid; it < 64 * 16; it += 256) {
            int r  = it >> 4;
            int c4 = (it & 15) * 4;
            float4 kv = *(const float4*)&Kp[(size_t)(j0 + r) * 64 + c4];
            Ks[r*65 + c4 + 0] = kv.x;
            Ks[r*65 + c4 + 1] = kv.y;
            Ks[r*65 + c4 + 2] = kv.z;
            Ks[r*65 + c4 + 3] = kv.w;
            *(float4*)&Vs[r*64 + c4] = *(const float4*)&Vp[(size_t)(j0 + r) * 64 + c4];
        }
        __syncthreads();

        // S = Q K^T (4x4 per thread)
        float s[4][4];
#pragma unroll
        for (int i = 0; i < 4; i++)
#pragma unroll
            for (int j = 0; j < 4; j++) s[i][j] = 0.f;

#pragma unroll 16
        for (int d = 0; d < 64; d++) {
            float qv[4], kv[4];
#pragma unroll
            for (int i = 0; i < 4; i++) qv[i] = Qs[(ty*4 + i)*65 + d];
#pragma unroll
            for (int j = 0; j < 4; j++) kv[j] = Ks[(tx*4 + j)*65 + d];
#pragma unroll
            for (int i = 0; i < 4; i++)
#pragma unroll
                for (int j = 0; j < 4; j++) s[i][j] += qv[i] * kv[j];
        }

        // scale + causal mask (only diagonal tile needs it)
        const bool diag = (jt == qt);
#pragma unroll
        for (int i = 0; i < 4; i++)
#pragma unroll
            for (int j = 0; j < 4; j++) {
                s[i][j] *= 0.125f;
                if (diag && (tx*4 + j) > (ty*4 + i)) s[i][j] = -INFINITY;
            }

        // Online softmax
#pragma unroll
        for (int i = 0; i < 4; i++) {
            float rm = fmaxf(fmaxf(s[i][0], s[i][1]), fmaxf(s[i][2], s[i][3]));
#pragma unroll
            for (int off = 1; off < 16; off <<= 1)
                rm = fmaxf(rm, __shfl_xor_sync(0xffffffffu, rm, off));
            float mn = fmaxf(m_i[i], rm);
            float p0 = __expf(s[i][0] - mn);
            float p1 = __expf(s[i][1] - mn);
            float p2 = __expf(s[i][2] - mn);
            float p3 = __expf(s[i][3] - mn);
            float rs = (p0 + p1) + (p2 + p3);
#pragma unroll
            for (int off = 1; off < 16; off <<= 1)
                rs += __shfl_xor_sync(0xffffffffu, rs, off);
            float alpha = __expf(m_i[i] - mn);   // first tile: exp(-inf)=0
            l_i[i] = l_i[i] * alpha + rs;
            m_i[i] = mn;
#pragma unroll
            for (int j = 0; j < 4; j++) acc[i][j] *= alpha;
            s[i][0] = p0; s[i][1] = p1; s[i][2] = p2; s[i][3] = p3;
        }

        // Stage P into smem (reuse Ks)
        __syncthreads();
#pragma unroll
        for (int i = 0; i < 4; i++)
#pragma unroll
            for (int j = 0; j < 4; j++)
                Ks[(ty*4 + i)*65 + tx*4 + j] = s[i][j];
        __syncthreads();

        // O += P @ V
#pragma unroll 16
        for (int k = 0; k < 64; k++) {
            float pv[4];
#pragma unroll
            for (int i = 0; i < 4; i++) pv[i] = Ks[(ty*4 + i)*65 + k];
            float4 vv = *(const float4*)&Vs[k*64 + tx*4];
#pragma unroll
            for (int i = 0; i < 4; i++) {
                acc[i][0] += pv[i] * vv.x;
                acc[i][1] += pv[i] * vv.y;
                acc[i][2] += pv[i] * vv.z;
                acc[i][3] += pv[i] * vv.w;
            }
        }
    }

    // Finalize + write to g_y in [B,T,H*P]
#pragma unroll
    for (int i = 0; i < 4; i++) {
        float inv = 1.f / l_i[i];
        int qg = q0 + ty*4 + i;
        float4 o = make_float4(acc[i][0]*inv, acc[i][1]*inv,
                               acc[i][2]*inv, acc[i][3]*inv);
        *(float4*)&g_y[((size_t)(b * T_ + qg)) * D_ + h*64 + tx*4] = o;
    }
}

// ---------------------------------------------------------------------------
extern "C" void kernel_launch(void* const* d_in, const int* in_sizes, int n_in,
                              void* d_out, int out_size)
{
    const float* x  = (const float*)d_in[0];
    // d_in[1] = attn_mask (static tril; causal handled analytically)
    const float* Wq = (const float*)d_in[2];
    const float* Wk = (const float*)d_in[3];
    const float* Wv = (const float*)d_in[4];
    const float* Wo = (const float*)d_in[5];
    float* out = (float*)d_out;

    dim3 blk(256);

    // QKV projections (fused, grid.z selects weight/output)
    gemm_kernel<0><<<dim3(8, 64, 3), blk>>>(x, Wq, Wk, Wv, nullptr);

    // Flash attention
    const int smem_bytes = ATTN_SMEM_FLOATS * sizeof(float);
    cudaFuncSetAttribute(attn_kernel,
                         cudaFuncAttributeMaxDynamicSharedMemorySize, smem_bytes);
    attn_kernel<<<dim3(T_/64, B_*H_), blk, smem_bytes>>>();

    // Output projection
    gemm_kernel<1><<<dim3(8, 64, 1), blk>>>(nullptr, Wo, nullptr, nullptr, out);
}

// round 2
// speedup vs baseline: 1.6223x; 1.6223x over previous
#include <cuda_runtime.h>
#include <math.h>
#include <stdint.h>

#define B_ 4
#define T_ 2048
#define D_ 1024
#define H_ 16
#define P_ 64
#define M_ (B_*T_)   // 8192

// Scratch (allocation-free rule: __device__ globals)
__device__ float g_q[(size_t)B_*H_*T_*P_];
__device__ float g_k[(size_t)B_*H_*T_*P_];
__device__ float g_v[(size_t)B_*H_*T_*P_];
__device__ float g_y[(size_t)M_*D_];

// ---------------------------------------------------------------------------
// Helpers
// ---------------------------------------------------------------------------
__device__ __forceinline__ uint32_t f2tf32(float x) {
    uint32_t r;
    asm("cvt.rna.tf32.f32 %0, %1;" : "=r"(r) : "f"(x));
    return r;
}
__device__ __forceinline__ uint32_t smem_u32(const void* p) {
    return (uint32_t)__cvta_generic_to_shared(p);
}
__device__ __forceinline__ void ldsm4(uint32_t& r0, uint32_t& r1,
                                      uint32_t& r2, uint32_t& r3, uint32_t addr) {
    asm volatile("ldmatrix.sync.aligned.m8n8.x4.shared.b16 {%0,%1,%2,%3}, [%4];"
                 : "=r"(r0), "=r"(r1), "=r"(r2), "=r"(r3) : "r"(addr));
}
__device__ __forceinline__ void mma_tf32(float c[4], const uint32_t a[4],
                                         uint32_t b0, uint32_t b1) {
    asm volatile(
        "mma.sync.aligned.m16n8k8.row.col.f32.tf32.tf32.f32 "
        "{%0,%1,%2,%3}, {%4,%5,%6,%7}, {%8,%9}, {%0,%1,%2,%3};"
        : "+f"(c[0]), "+f"(c[1]), "+f"(c[2]), "+f"(c[3])
        : "r"(a[0]), "r"(a[1]), "r"(a[2]), "r"(a[3]), "r"(b0), "r"(b1));
}

// ---------------------------------------------------------------------------
// tf32 tensor-core GEMM: C[M,1024] = A[M,1024] * W[1024,1024]
// Block tile 128x128, K-tile 32. 256 threads = 8 warps (2M x 4N), warp 64x32.
// MODE 0: A = x, blockIdx.z selects (Wq->g_q, Wk->g_k, Wv->g_v),
//         epilogue scatters to [B,H,T,P].
// MODE 1: A = g_y, W = W0, C = d_out row-major.
// ---------------------------------------------------------------------------
#define LDA 36            // A smem row stride (floats); 144B rows -> ldmatrix conflict-free
#define LDB 136           // B smem row stride (floats); scalar b-loads conflict-free
#define A_TILE (128*LDA)  // 4608 floats
#define B_TILE (32*LDB)   // 4352 floats
#define GEMM_SMEM_BYTES ((2*A_TILE + 2*B_TILE) * 4)   // 71680 B
#define NKT 32

template <int MODE>
__global__ __launch_bounds__(256, 1)
void gemm_tc(const float* __restrict__ X,
             const float* __restrict__ W0,
             const float* __restrict__ W1,
             const float* __restrict__ W2,
             float* __restrict__ outp)
{
    extern __shared__ float sm_g[];
    // layout: [A0][A1][B0][B1]

    const int K = 1024, N = 1024;
    const int m0 = blockIdx.y * 128;
    const int n0 = blockIdx.x * 128;

    const float* Ap;
    const float* W;
    float* Cq = nullptr;
    if (MODE == 0) {
        Ap = X;
        int z = blockIdx.z;
        W  = (z == 0) ? W0 : ((z == 1) ? W1 : W2);
        Cq = (z == 0) ? g_q : ((z == 1) ? g_k : g_v);
    } else {
        Ap = g_y;
        W  = W0;
    }

    const int tid  = threadIdx.x;
    const int lane = tid & 31;
    const int warp = tid >> 5;
    const int wm = (warp >> 2) * 64;   // warp M offset in tile
    const int wn = (warp & 3) * 32;    // warp N offset in tile
    const int gid = lane >> 2;         // 0..7
    const int tig = lane & 3;          // 0..3

    // ldmatrix per-lane source row/col within the A tile
    const int aRow    = (lane < 16) ? lane : (lane - 16);
    const int aColOff = (lane < 16) ? 0 : 4;

    float acc[4][4][4];
#pragma unroll
    for (int mf = 0; mf < 4; mf++)
#pragma unroll
        for (int nf = 0; nf < 4; nf++)
#pragma unroll
            for (int i = 0; i < 4; i++) acc[mf][nf][i] = 0.f;

    // ---- tile load helpers (inline) ----
    // A tile: 128 rows x 32 cols -> 4 float4/thread; B tile: 32 x 128 -> 4 float4/thread
    auto ldg_tile = [&](int kt, float4 sa[4], float4 sb[4]) {
#pragma unroll
        for (int r = 0; r < 4; r++) {
            int lin  = tid + r * 256;
            int arow = lin >> 3;
            int ac4  = (lin & 7) * 4;
            sa[r] = *(const float4*)&Ap[(size_t)(m0 + arow) * K + kt * 32 + ac4];
            int brow = lin >> 5;
            int bc4  = (lin & 31) * 4;
            sb[r] = *(const float4*)&W[(size_t)(kt * 32 + brow) * N + n0 + bc4];
        }
    };
    auto sts_tile = [&](int buf, const float4 sa[4], const float4 sb[4]) {
        float* As = sm_g + buf * A_TILE;
        float* Bs = sm_g + 2 * A_TILE + buf * B_TILE;
#pragma unroll
        for (int r = 0; r < 4; r++) {
            int lin  = tid + r * 256;
            int arow = lin >> 3;
            int ac4  = (lin & 7) * 4;
            uint4 av = make_uint4(f2tf32(sa[r].x), f2tf32(sa[r].y),
                                  f2tf32(sa[r].z), f2tf32(sa[r].w));
            *(uint4*)&As[arow * LDA + ac4] = av;
            int brow = lin >> 5;
            int bc4  = (lin & 31) * 4;
            uint4 bv = make_uint4(f2tf32(sb[r].x), f2tf32(sb[r].y),
                                  f2tf32(sb[r].z), f2tf32(sb[r].w));
            *(uint4*)&Bs[brow * LDB + bc4] = bv;
        }
    };

    {
        float4 sa[4], sb[4];
        ldg_tile(0, sa, sb);
        sts_tile(0, sa, sb);
    }
    __syncthreads();

    int buf = 0;
    for (int kt = 0; kt < NKT; kt++) {
        float4 sa[4], sb[4];
        if (kt + 1 < NKT) ldg_tile(kt + 1, sa, sb);

        // compute on buf
        const float* As = sm_g + buf * A_TILE;
        const float* Bs = sm_g + 2 * A_TILE + buf * B_TILE;
        uint32_t aBase = smem_u32(As + (wm + aRow) * LDA + aColOff);
#pragma unroll
        for (int kf = 0; kf < 4; kf++) {
            uint32_t a[4][4];
#pragma unroll
            for (int mf = 0; mf < 4; mf++)
                ldsm4(a[mf][0], a[mf][1], a[mf][2], a[mf][3],
                      aBase + (uint32_t)(mf * 16 * LDA + kf * 8) * 4u);
            uint32_t b[4][2];
#pragma unroll
            for (int nf = 0; nf < 4; nf++) {
                const uint32_t* bp =
                    (const uint32_t*)(Bs + (kf * 8 + tig) * LDB + wn + nf * 8 + gid);
                b[nf][0] = bp[0];
                b[nf][1] = bp[4 * LDB];
            }
#pragma unroll
            for (int mf = 0; mf < 4; mf++)
#pragma unroll
                for (int nf = 0; nf < 4; nf++)
                    mma_tf32(acc[mf][nf], a[mf], b[nf][0], b[nf][1]);
        }

        if (kt + 1 < NKT) sts_tile(buf ^ 1, sa, sb);
        buf ^= 1;
        __syncthreads();
    }

    // Epilogue: c0,c1 at (row, col..col+1); c2,c3 at (row+8, col..col+1)
#pragma unroll
    for (int mf = 0; mf < 4; mf++) {
#pragma unroll
        for (int nf = 0; nf < 4; nf++) {
            int row = m0 + wm + mf * 16 + gid;
            int col = n0 + wn + nf * 8 + tig * 2;
#pragma unroll
            for (int half = 0; half < 2; half++) {
                int rr = row + half * 8;
                float2 v = make_float2(acc[mf][nf][half * 2],
                                       acc[mf][nf][half * 2 + 1]);
                if (MODE == 0) {
                    int b = rr >> 11;
                    int t = rr & 2047;
                    int h = col >> 6;
                    int p = col & 63;
                    *(float2*)&Cq[(((size_t)(b * H_ + h) * T_ + t) * P_ + p)] = v;
                } else {
                    *(float2*)&outp[(size_t)rr * 1024 + col] = v;
                }
            }
        }
    }
}

// ---------------------------------------------------------------------------
// Flash attention, causal. Q/K/V in [B,H,T,P] layout (P=64). (unchanged)
// ---------------------------------------------------------------------------
#define ATTN_SMEM_FLOATS (2*64*65 + 64*64)

__global__ __launch_bounds__(256, 2)
void attn_kernel()
{
    extern __shared__ float sm[];
    float* Qs = sm;               // [64][65] padded
    float* Ks = sm + 64*65;       // [64][65] padded, reused for P
    float* Vs = sm + 2*64*65;     // [64][64]

    const int bh = blockIdx.y;
    const int b  = bh >> 4;
    const int h  = bh & 15;
    const int qt = blockIdx.x;
    const int q0 = qt * 64;

    const size_t base = (size_t)bh * T_ * P_;
    const float* Qp = g_q + base;
    const float* Kp = g_k + base;
    const float* Vp = g_v + base;

    const int tid = threadIdx.x;
    const int tx = tid & 15;
    const int ty = tid >> 4;

    for (int it = tid; it < 64 * 16; it += 256) {
        int r  = it >> 4;
        int c4 = (it & 15) * 4;
        float4 v = *(const float4*)&Qp[(size_t)(q0 + r) * 64 + c4];
        Qs[r*65 + c4 + 0] = v.x;
        Qs[r*65 + c4 + 1] = v.y;
        Qs[r*65 + c4 + 2] = v.z;
        Qs[r*65 + c4 + 3] = v.w;
    }

    float acc[4][4];
    float m_i[4], l_i[4];
#pragma unroll
    for (int i = 0; i < 4; i++) {
        m_i[i] = -INFINITY;
        l_i[i] = 0.f;
#pragma unroll
        for (int j = 0; j < 4; j++) acc[i][j] = 0.f;
    }

    for (int jt = 0; jt <= qt; jt++) {
        const int j0 = jt * 64;
        __syncthreads();
        for (int it = tid; it < 64 * 16; it += 256) {
            int r  = it >> 4;
            int c4 = (it & 15) * 4;
            float4 kv = *(const float4*)&Kp[(size_t)(j0 + r) * 64 + c4];
            Ks[r*65 + c4 + 0] = kv.x;
            Ks[r*65 + c4 + 1] = kv.y;
            Ks[r*65 + c4 + 2] = kv.z;
            Ks[r*65 + c4 + 3] = kv.w;
            *(float4*)&Vs[r*64 + c4] = *(const float4*)&Vp[(size_t)(j0 + r) * 64 + c4];
        }
        __syncthreads();

        float s[4][4];
#pragma unroll
        for (int i = 0; i < 4; i++)
#pragma unroll
            for (int j = 0; j < 4; j++) s[i][j] = 0.f;

#pragma unroll 16
        for (int d = 0; d < 64; d++) {
            float qv[4], kv[4];
#pragma unroll
            for (int i = 0; i < 4; i++) qv[i] = Qs[(ty*4 + i)*65 + d];
#pragma unroll
            for (int j = 0; j < 4; j++) kv[j] = Ks[(tx*4 + j)*65 + d];
#pragma unroll
            for (int i = 0; i < 4; i++)
#pragma unroll
                for (int j = 0; j < 4; j++) s[i][j] += qv[i] * kv[j];
        }

        const bool diag = (jt == qt);
#pragma unroll
        for (int i = 0; i < 4; i++)
#pragma unroll
            for (int j = 0; j < 4; j++) {
                s[i][j] *= 0.125f;
                if (diag && (tx*4 + j) > (ty*4 + i)) s[i][j] = -INFINITY;
            }

#pragma unroll
        for (int i = 0; i < 4; i++) {
            float rm = fmaxf(fmaxf(s[i][0], s[i][1]), fmaxf(s[i][2], s[i][3]));
#pragma unroll
            for (int off = 1; off < 16; off <<= 1)
                rm = fmaxf(rm, __shfl_xor_sync(0xffffffffu, rm, off));
            float mn = fmaxf(m_i[i], rm);
            float p0 = __expf(s[i][0] - mn);
            float p1 = __expf(s[i][1] - mn);
            float p2 = __expf(s[i][2] - mn);
            float p3 = __expf(s[i][3] - mn);
            float rs = (p0 + p1) + (p2 + p3);
#pragma unroll
            for (int off = 1; off < 16; off <<= 1)
                rs += __shfl_xor_sync(0xffffffffu, rs, off);
            float alpha = __expf(m_i[i] - mn);
            l_i[i] = l_i[i] * alpha + rs;
            m_i[i] = mn;
#pragma unroll
            for (int j = 0; j < 4; j++) acc[i][j] *= alpha;
            s[i][0] = p0; s[i][1] = p1; s[i][2] = p2; s[i][3] = p3;
        }

        __syncthreads();
#pragma unroll
        for (int i = 0; i < 4; i++)
#pragma unroll
            for (int j = 0; j < 4; j++)
                Ks[(ty*4 + i)*65 + tx*4 + j] = s[i][j];
        __syncthreads();

#pragma unroll 16
        for (int k = 0; k < 64; k++) {
            float pv[4];
#pragma unroll
            for (int i = 0; i < 4; i++) pv[i] = Ks[(ty*4 + i)*65 + k];
            float4 vv = *(const float4*)&Vs[k*64 + tx*4];
#pragma unroll
            for (int i = 0; i < 4; i++) {
                acc[i][0] += pv[i] * vv.x;
                acc[i][1] += pv[i] * vv.y;
                acc[i][2] += pv[i] * vv.z;
                acc[i][3] += pv[i] * vv.w;
            }
        }
    }

#pragma unroll
    for (int i = 0; i < 4; i++) {
        float inv = 1.f / l_i[i];
        int qg = q0 + ty*4 + i;
        float4 o = make_float4(acc[i][0]*inv, acc[i][1]*inv,
                               acc[i][2]*inv, acc[i][3]*inv);
        *(float4*)&g_y[((size_t)(b * T_ + qg)) * D_ + h*64 + tx*4] = o;
    }
}

// ---------------------------------------------------------------------------
extern "C" void kernel_launch(void* const* d_in, const int* in_sizes, int n_in,
                              void* d_out, int out_size)
{
    const float* x  = (const float*)d_in[0];
    // d_in[1] = attn_mask (static tril; causal handled analytically)
    const float* Wq = (const float*)d_in[2];
    const float* Wk = (const float*)d_in[3];
    const float* Wv = (const float*)d_in[4];
    const float* Wo = (const float*)d_in[5];
    float* out = (float*)d_out;

    cudaFuncSetAttribute(gemm_tc<0>, cudaFuncAttributeMaxDynamicSharedMemorySize,
                         GEMM_SMEM_BYTES);
    cudaFuncSetAttribute(gemm_tc<1>, cudaFuncAttributeMaxDynamicSharedMemorySize,
                         GEMM_SMEM_BYTES);

    // QKV projections (tf32 tensor cores)
    gemm_tc<0><<<dim3(8, 64, 3), 256, GEMM_SMEM_BYTES>>>(x, Wq, Wk, Wv, nullptr);

    // Flash attention (fp32 SIMT, unchanged this round)
    const int smem_bytes = ATTN_SMEM_FLOATS * sizeof(float);
    cudaFuncSetAttribute(attn_kernel,
                         cudaFuncAttributeMaxDynamicSharedMemorySize, smem_bytes);
    attn_kernel<<<dim3(T_/64, B_*H_), 256, smem_bytes>>>();

    // Output projection
    gemm_tc<1><<<dim3(8, 64, 1), 256, GEMM_SMEM_BYTES>>>(nullptr, Wo, nullptr, nullptr, out);
}

// round 3
// speedup vs baseline: 2.3245x; 1.4328x over previous
#include <cuda_runtime.h>
#include <math.h>
#include <stdint.h>

#define B_ 4
#define T_ 2048
#define D_ 1024
#define H_ 16
#define P_ 64
#define M_ (B_*T_)   // 8192

// Scratch (allocation-free rule: __device__ globals)
__device__ float g_q[(size_t)B_*H_*T_*P_];
__device__ float g_k[(size_t)B_*H_*T_*P_];
__device__ float g_v[(size_t)B_*H_*T_*P_];
__device__ float g_y[(size_t)M_*D_];

// ---------------------------------------------------------------------------
// Helpers
// ---------------------------------------------------------------------------
__device__ __forceinline__ uint32_t f2tf32(float x) {
    uint32_t r;
    asm("cvt.rna.tf32.f32 %0, %1;" : "=r"(r) : "f"(x));
    return r;
}
__device__ __forceinline__ uint32_t smem_u32(const void* p) {
    return (uint32_t)__cvta_generic_to_shared(p);
}
__device__ __forceinline__ void ldsm4(uint32_t& r0, uint32_t& r1,
                                      uint32_t& r2, uint32_t& r3, uint32_t addr) {
    asm volatile("ldmatrix.sync.aligned.m8n8.x4.shared.b16 {%0,%1,%2,%3}, [%4];"
                 : "=r"(r0), "=r"(r1), "=r"(r2), "=r"(r3) : "r"(addr));
}
__device__ __forceinline__ void mma_tf32(float c[4], const uint32_t a[4],
                                         uint32_t b0, uint32_t b1) {
    asm volatile(
        "mma.sync.aligned.m16n8k8.row.col.f32.tf32.tf32.f32 "
        "{%0,%1,%2,%3}, {%4,%5,%6,%7}, {%8,%9}, {%0,%1,%2,%3};"
        : "+f"(c[0]), "+f"(c[1]), "+f"(c[2]), "+f"(c[3])
        : "r"(a[0]), "r"(a[1]), "r"(a[2]), "r"(a[3]), "r"(b0), "r"(b1));
}

// ---------------------------------------------------------------------------
// tf32 tensor-core GEMM (unchanged from R2)
// ---------------------------------------------------------------------------
#define LDA 36
#define LDB 136
#define A_TILE (128*LDA)
#define B_TILE (32*LDB)
#define GEMM_SMEM_BYTES ((2*A_TILE + 2*B_TILE) * 4)
#define NKT 32

template <int MODE>
__global__ __launch_bounds__(256, 1)
void gemm_tc(const float* __restrict__ X,
             const float* __restrict__ W0,
             const float* __restrict__ W1,
             const float* __restrict__ W2,
             float* __restrict__ outp)
{
    extern __shared__ float sm_g[];

    const int K = 1024, N = 1024;
    const int m0 = blockIdx.y * 128;
    const int n0 = blockIdx.x * 128;

    const float* Ap;
    const float* W;
    float* Cq = nullptr;
    if (MODE == 0) {
        Ap = X;
        int z = blockIdx.z;
        W  = (z == 0) ? W0 : ((z == 1) ? W1 : W2);
        Cq = (z == 0) ? g_q : ((z == 1) ? g_k : g_v);
    } else {
        Ap = g_y;
        W  = W0;
    }

    const int tid  = threadIdx.x;
    const int lane = tid & 31;
    const int warp = tid >> 5;
    const int wm = (warp >> 2) * 64;
    const int wn = (warp & 3) * 32;
    const int gid = lane >> 2;
    const int tig = lane & 3;

    const int aRow    = (lane < 16) ? lane : (lane - 16);
    const int aColOff = (lane < 16) ? 0 : 4;

    float acc[4][4][4];
#pragma unroll
    for (int mf = 0; mf < 4; mf++)
#pragma unroll
        for (int nf = 0; nf < 4; nf++)
#pragma unroll
            for (int i = 0; i < 4; i++) acc[mf][nf][i] = 0.f;

    auto ldg_tile = [&](int kt, float4 sa[4], float4 sb[4]) {
#pragma unroll
        for (int r = 0; r < 4; r++) {
            int lin  = tid + r * 256;
            int arow = lin >> 3;
            int ac4  = (lin & 7) * 4;
            sa[r] = *(const float4*)&Ap[(size_t)(m0 + arow) * K + kt * 32 + ac4];
            int brow = lin >> 5;
            int bc4  = (lin & 31) * 4;
            sb[r] = *(const float4*)&W[(size_t)(kt * 32 + brow) * N + n0 + bc4];
        }
    };
    auto sts_tile = [&](int buf, const float4 sa[4], const float4 sb[4]) {
        float* As = sm_g + buf * A_TILE;
        float* Bs = sm_g + 2 * A_TILE + buf * B_TILE;
#pragma unroll
        for (int r = 0; r < 4; r++) {
            int lin  = tid + r * 256;
            int arow = lin >> 3;
            int ac4  = (lin & 7) * 4;
            uint4 av = make_uint4(f2tf32(sa[r].x), f2tf32(sa[r].y),
                                  f2tf32(sa[r].z), f2tf32(sa[r].w));
            *(uint4*)&As[arow * LDA + ac4] = av;
            int brow = lin >> 5;
            int bc4  = (lin & 31) * 4;
            uint4 bv = make_uint4(f2tf32(sb[r].x), f2tf32(sb[r].y),
                                  f2tf32(sb[r].z), f2tf32(sb[r].w));
            *(uint4*)&Bs[brow * LDB + bc4] = bv;
        }
    };

    {
        float4 sa[4], sb[4];
        ldg_tile(0, sa, sb);
        sts_tile(0, sa, sb);
    }
    __syncthreads();

    int buf = 0;
    for (int kt = 0; kt < NKT; kt++) {
        float4 sa[4], sb[4];
        if (kt + 1 < NKT) ldg_tile(kt + 1, sa, sb);

        const float* As = sm_g + buf * A_TILE;
        const float* Bs = sm_g + 2 * A_TILE + buf * B_TILE;
        uint32_t aBase = smem_u32(As + (wm + aRow) * LDA + aColOff);
#pragma unroll
        for (int kf = 0; kf < 4; kf++) {
            uint32_t a[4][4];
#pragma unroll
            for (int mf = 0; mf < 4; mf++)
                ldsm4(a[mf][0], a[mf][1], a[mf][2], a[mf][3],
                      aBase + (uint32_t)(mf * 16 * LDA + kf * 8) * 4u);
            uint32_t b[4][2];
#pragma unroll
            for (int nf = 0; nf < 4; nf++) {
                const uint32_t* bp =
                    (const uint32_t*)(Bs + (kf * 8 + tig) * LDB + wn + nf * 8 + gid);
                b[nf][0] = bp[0];
                b[nf][1] = bp[4 * LDB];
            }
#pragma unroll
            for (int mf = 0; mf < 4; mf++)
#pragma unroll
                for (int nf = 0; nf < 4; nf++)
                    mma_tf32(acc[mf][nf], a[mf], b[nf][0], b[nf][1]);
        }

        if (kt + 1 < NKT) sts_tile(buf ^ 1, sa, sb);
        buf ^= 1;
        __syncthreads();
    }

#pragma unroll
    for (int mf = 0; mf < 4; mf++) {
#pragma unroll
        for (int nf = 0; nf < 4; nf++) {
            int row = m0 + wm + mf * 16 + gid;
            int col = n0 + wn + nf * 8 + tig * 2;
#pragma unroll
            for (int half = 0; half < 2; half++) {
                int rr = row + half * 8;
                float2 v = make_float2(acc[mf][nf][half * 2],
                                       acc[mf][nf][half * 2 + 1]);
                if (MODE == 0) {
                    int b = rr >> 11;
                    int t = rr & 2047;
                    int h = col >> 6;
                    int p = col & 63;
                    *(float2*)&Cq[(((size_t)(b * H_ + h) * T_ + t) * P_ + p)] = v;
                } else {
                    *(float2*)&outp[(size_t)rr * 1024 + col] = v;
                }
            }
        }
    }
}

// ---------------------------------------------------------------------------
// tf32 tensor-core flash attention, causal.
// Block: 256 thr = 8 warps; 128 q-rows/block (16 per warp), kv tiles of 64.
// Each warp owns its 16 rows across the full 64 kv columns -> softmax
// reductions are 4-lane shfls only. P round-trips through warp-local smem.
// ---------------------------------------------------------------------------
#define LDQ 68
#define LDK 68
#define LDV 72
#define LDP 68
#define ATTN_SMEM_FLOATS (128*LDQ + 64*LDK + 64*LDV + 128*LDP)  // 26368
#define ATTN_SMEM_BYTES  (ATTN_SMEM_FLOATS*4)                   // 105472

__global__ __launch_bounds__(256, 1)
void attn_tc()
{
    extern __shared__ float sm[];
    float* Qs = sm;                      // [128][LDQ] tf32
    float* Ks = Qs + 128*LDQ;            // [64(kv)][LDK] tf32 (natural layout)
    float* Vs = Ks + 64*LDK;             // [64(kv)][LDV] tf32
    float* Ps = Vs + 64*LDV;             // [128][LDP] tf32

    const int bh = blockIdx.y;
    const int b  = bh >> 4;
    const int h  = bh & 15;
    const int qt = (int)gridDim.x - 1 - (int)blockIdx.x;  // heavy blocks first
    const int q0 = qt * 128;

    const size_t base = (size_t)bh * T_ * P_;
    const float* Qp = g_q + base;
    const float* Kp = g_k + base;
    const float* Vp = g_v + base;

    const int tid  = threadIdx.x;
    const int lane = tid & 31;
    const int warp = tid >> 5;
    const int gid  = lane >> 2;
    const int tig  = lane & 3;
    const int aRow    = (lane < 16) ? lane : (lane - 16);
    const int aColOff = (lane < 16) ? 0 : 4;

    // Load Q tile (128x64), convert to tf32
    for (int it = tid; it < 128 * 16; it += 256) {
        int r  = it >> 4;
        int c4 = (it & 15) * 4;
        float4 v = *(const float4*)&Qp[(size_t)(q0 + r) * 64 + c4];
        *(uint4*)&Qs[r * LDQ + c4] =
            make_uint4(f2tf32(v.x), f2tf32(v.y), f2tf32(v.z), f2tf32(v.w));
    }

    float accO[8][4];
#pragma unroll
    for (int nf = 0; nf < 8; nf++)
#pragma unroll
        for (int i = 0; i < 4; i++) accO[nf][i] = 0.f;
    float mr0 = -INFINITY, mr1 = -INFINITY, l0 = 0.f, l1 = 0.f;

    const float sc = 0.18033688011112042f;   // 0.125 * log2(e)
    const int ntiles = 2 * qt + 2;

    for (int jt = 0; jt < ntiles; jt++) {
        const int j0 = jt * 64;
        __syncthreads();   // prev iter done with Ks/Vs; Q covered for jt=0
        for (int it = tid; it < 64 * 16; it += 256) {
            int r  = it >> 4;
            int c4 = (it & 15) * 4;
            float4 kv = *(const float4*)&Kp[(size_t)(j0 + r) * 64 + c4];
            *(uint4*)&Ks[r * LDK + c4] =
                make_uint4(f2tf32(kv.x), f2tf32(kv.y), f2tf32(kv.z), f2tf32(kv.w));
            float4 vv = *(const float4*)&Vp[(size_t)(j0 + r) * 64 + c4];
            *(uint4*)&Vs[r * LDV + c4] =
                make_uint4(f2tf32(vv.x), f2tf32(vv.y), f2tf32(vv.z), f2tf32(vv.w));
        }
        __syncthreads();

        // ---- S = Q K^T  (warp: 16 rows x 64 cols) ----
        float c[8][4];
#pragma unroll
        for (int nf = 0; nf < 8; nf++)
#pragma unroll
            for (int i = 0; i < 4; i++) c[nf][i] = 0.f;

        uint32_t aBaseQ = smem_u32(Qs + (warp * 16 + aRow) * LDQ + aColOff);
#pragma unroll
        for (int kf = 0; kf < 8; kf++) {
            uint32_t a[4];
            ldsm4(a[0], a[1], a[2], a[3], aBaseQ + (uint32_t)(kf * 8) * 4u);
#pragma unroll
            for (int nf = 0; nf < 8; nf++) {
                const uint32_t* bp =
                    (const uint32_t*)(Ks + (nf * 8 + gid) * LDK + kf * 8 + tig);
                mma_tf32(c[nf], a, bp[0], bp[4]);
            }
        }

        // ---- causal mask (last two tiles only) ----
        if (jt >= 2 * qt) {
            int row0 = q0 + warp * 16 + gid;
#pragma unroll
            for (int nf = 0; nf < 8; nf++) {
                int col = j0 + nf * 8 + tig * 2;
                if (col     > row0)     c[nf][0] = -INFINITY;
                if (col + 1 > row0)     c[nf][1] = -INFINITY;
                if (col     > row0 + 8) c[nf][2] = -INFINITY;
                if (col + 1 > row0 + 8) c[nf][3] = -INFINITY;
            }
        }

        // ---- online softmax (raw-score units; scale folded into exp2) ----
        float rm0 = -INFINITY, rm1 = -INFINITY;
#pragma unroll
        for (int nf = 0; nf < 8; nf++) {
            rm0 = fmaxf(rm0, fmaxf(c[nf][0], c[nf][1]));
            rm1 = fmaxf(rm1, fmaxf(c[nf][2], c[nf][3]));
        }
#pragma unroll
        for (int off = 1; off < 4; off <<= 1) {
            rm0 = fmaxf(rm0, __shfl_xor_sync(0xffffffffu, rm0, off));
            rm1 = fmaxf(rm1, __shfl_xor_sync(0xffffffffu, rm1, off));
        }
        float mn0 = fmaxf(mr0, rm0);
        float mn1 = fmaxf(mr1, rm1);
        float al0 = exp2f((mr0 - mn0) * sc);
        float al1 = exp2f((mr1 - mn1) * sc);
        float rs0 = 0.f, rs1 = 0.f;
#pragma unroll
        for (int nf = 0; nf < 8; nf++) {
            c[nf][0] = exp2f((c[nf][0] - mn0) * sc);
            c[nf][1] = exp2f((c[nf][1] - mn0) * sc);
            c[nf][2] = exp2f((c[nf][2] - mn1) * sc);
            c[nf][3] = exp2f((c[nf][3] - mn1) * sc);
            rs0 += c[nf][0] + c[nf][1];
            rs1 += c[nf][2] + c[nf][3];
        }
#pragma unroll
        for (int off = 1; off < 4; off <<= 1) {
            rs0 += __shfl_xor_sync(0xffffffffu, rs0, off);
            rs1 += __shfl_xor_sync(0xffffffffu, rs1, off);
        }
        l0 = l0 * al0 + rs0;
        l1 = l1 * al1 + rs1;
        mr0 = mn0;
        mr1 = mn1;
#pragma unroll
        for (int nf = 0; nf < 8; nf++) {
            accO[nf][0] *= al0;
            accO[nf][1] *= al0;
            accO[nf][2] *= al1;
            accO[nf][3] *= al1;
        }

        // ---- stage P (warp-local rows -> only __syncwarp) ----
        {
            float* p0 = Ps + (warp * 16 + gid) * LDP + tig * 2;
            float* p1 = p0 + 8 * LDP;
#pragma unroll
            for (int nf = 0; nf < 8; nf++) {
                ((uint32_t*)p0)[nf * 8]     = f2tf32(c[nf][0]);
                ((uint32_t*)p0)[nf * 8 + 1] = f2tf32(c[nf][1]);
                ((uint32_t*)p1)[nf * 8]     = f2tf32(c[nf][2]);
                ((uint32_t*)p1)[nf * 8 + 1] = f2tf32(c[nf][3]);
            }
        }
        __syncwarp();

        // ---- O += P @ V ----
        uint32_t aBaseP = smem_u32(Ps + (warp * 16 + aRow) * LDP + aColOff);
#pragma unroll
        for (int kf = 0; kf < 8; kf++) {
            uint32_t a[4];
            ldsm4(a[0], a[1], a[2], a[3], aBaseP + (uint32_t)(kf * 8) * 4u);
#pragma unroll
            for (int nf = 0; nf < 8; nf++) {
                const uint32_t* bp =
                    (const uint32_t*)(Vs + (kf * 8 + tig) * LDV + nf * 8 + gid);
                mma_tf32(accO[nf], a, bp[0], bp[4 * LDV]);
            }
        }
        __syncwarp();
    }

    // ---- finalize; write to g_y [B,T,H*P] ----
    float inv0 = 1.f / l0;
    float inv1 = 1.f / l1;
    int rowg = q0 + warp * 16 + gid;
    float* y0 = g_y + ((size_t)(b * T_ + rowg)) * D_ + h * 64 + tig * 2;
    float* y1 = y0 + 8 * (size_t)D_;
#pragma unroll
    for (int nf = 0; nf < 8; nf++) {
        *(float2*)&y0[nf * 8] = make_float2(accO[nf][0] * inv0, accO[nf][1] * inv0);
        *(float2*)&y1[nf * 8] = make_float2(accO[nf][2] * inv1, accO[nf][3] * inv1);
    }
}

// ---------------------------------------------------------------------------
extern "C" void kernel_launch(void* const* d_in, const int* in_sizes, int n_in,
                              void* d_out, int out_size)
{
    const float* x  = (const float*)d_in[0];
    const float* Wq = (const float*)d_in[2];
    const float* Wk = (const float*)d_in[3];
    const float* Wv = (const float*)d_in[4];
    const float* Wo = (const float*)d_in[5];
    float* out = (float*)d_out;

    cudaFuncSetAttribute(gemm_tc<0>, cudaFuncAttributeMaxDynamicSharedMemorySize,
                         GEMM_SMEM_BYTES);
    cudaFuncSetAttribute(gemm_tc<1>, cudaFuncAttributeMaxDynamicSharedMemorySize,
                         GEMM_SMEM_BYTES);
    cudaFuncSetAttribute(attn_tc, cudaFuncAttributeMaxDynamicSharedMemorySize,
                         ATTN_SMEM_BYTES);

    // QKV projections
    gemm_tc<0><<<dim3(8, 64, 3), 256, GEMM_SMEM_BYTES>>>(x, Wq, Wk, Wv, nullptr);

    // Flash attention (tf32 tensor cores)
    attn_tc<<<dim3(T_/128, B_*H_), 256, ATTN_SMEM_BYTES>>>();

    // Output projection
    gemm_tc<1><<<dim3(8, 64, 1), 256, GEMM_SMEM_BYTES>>>(nullptr, Wo, nullptr, nullptr, out);
}

// round 5
// speedup vs baseline: 3.0068x; 1.2935x over previous
#include <cuda_runtime.h>
#include <math.h>
#include <stdint.h>

#define B_ 4
#define T_ 2048
#define D_ 1024
#define H_ 16
#define P_ 64
#define M_ (B_*T_)   // 8192

// Scratch (allocation-free rule: __device__ globals)
__device__ float g_q[(size_t)B_*H_*T_*P_];
__device__ float g_k[(size_t)B_*H_*T_*P_];
__device__ float g_v[(size_t)B_*H_*T_*P_];
__device__ float g_y[(size_t)M_*D_];
__device__ float g_xr[(size_t)M_*D_];        // x rounded to tf32
__device__ float g_wr[(size_t)4*1024*1024];  // Wq,Wk,Wv,Wo rounded to tf32

// ---------------------------------------------------------------------------
// Helpers
// ---------------------------------------------------------------------------
__device__ __forceinline__ uint32_t f2tf32(float x) {
    uint32_t r;
    asm("cvt.rna.tf32.f32 %0, %1;" : "=r"(r) : "f"(x));
    return r;
}
__device__ __forceinline__ float f2tf32f(float x) {
    return __uint_as_float(f2tf32(x));
}
__device__ __forceinline__ uint32_t smem_u32(const void* p) {
    return (uint32_t)__cvta_generic_to_shared(p);
}
__device__ __forceinline__ void ldsm4(uint32_t& r0, uint32_t& r1,
                                      uint32_t& r2, uint32_t& r3, uint32_t addr) {
    asm volatile("ldmatrix.sync.aligned.m8n8.x4.shared.b16 {%0,%1,%2,%3}, [%4];"
                 : "=r"(r0), "=r"(r1), "=r"(r2), "=r"(r3) : "r"(addr));
}
__device__ __forceinline__ void mma_tf32(float c[4], const uint32_t a[4],
                                         uint32_t b0, uint32_t b1) {
    asm volatile(
        "mma.sync.aligned.m16n8k8.row.col.f32.tf32.tf32.f32 "
        "{%0,%1,%2,%3}, {%4,%5,%6,%7}, {%8,%9}, {%0,%1,%2,%3};"
        : "+f"(c[0]), "+f"(c[1]), "+f"(c[2]), "+f"(c[3])
        : "r"(a[0]), "r"(a[1]), "r"(a[2]), "r"(a[3]), "r"(b0), "r"(b1));
}
__device__ __forceinline__ void cp16(uint32_t dst, const void* src) {
    asm volatile("cp.async.cg.shared.global [%0], [%1], 16;"
                 :: "r"(dst), "l"(src));
}
__device__ __forceinline__ void cp_commit() {
    asm volatile("cp.async.commit_group;");
}
__device__ __forceinline__ void cp_wait0() {
    asm volatile("cp.async.wait_group 0;" ::: "memory");
}
__device__ __forceinline__ void sts128(uint32_t dst, float a, float b, float c, float d) {
    asm volatile("st.shared.v4.b32 [%0], {%1,%2,%3,%4};"
                 :: "r"(dst), "r"(__float_as_uint(a)), "r"(__float_as_uint(b)),
                    "r"(__float_as_uint(c)), "r"(__float_as_uint(d)));
}

// ---------------------------------------------------------------------------
// Prep: round x and all weights to tf32 once.
// ---------------------------------------------------------------------------
__global__ void prep_round(const float* __restrict__ x,
                           const float* __restrict__ wq,
                           const float* __restrict__ wk,
                           const float* __restrict__ wv,
                           const float* __restrict__ wo)
{
    int i4 = blockIdx.x * blockDim.x + threadIdx.x;   // one float4 each
    if (i4 < 2097152) {
        float4 v = ((const float4*)x)[i4];
        ((float4*)g_xr)[i4] = make_float4(f2tf32f(v.x), f2tf32f(v.y),
                                          f2tf32f(v.z), f2tf32f(v.w));
    } else {
        int j = i4 - 2097152;
        int w = j >> 18;           // 0..3
        int jj = j & 262143;
        const float* src = (w == 0) ? wq : (w == 1) ? wk : (w == 2) ? wv : wo;
        float4 v = ((const float4*)src)[jj];
        ((float4*)(g_wr + (size_t)w * 1048576))[jj] =
            make_float4(f2tf32f(v.x), f2tf32f(v.y), f2tf32f(v.z), f2tf32f(v.w));
    }
}

// ---------------------------------------------------------------------------
// tf32 tensor-core GEMM: C[M,1024] = A[M,1024] * W[1024,1024]
// Block tile 256x128, K-tile 32. 512 threads = 16 warps (4M x 4N), warp 64x32.
// A via cp.async (pre-rounded tf32, selected in-kernel), W via column LDG.32
// -> swizzled transposed smem (Bt[n][k]) read with ldmatrix.x4.
// MODE 0: A = g_xr, z selects W (g_wr) and output (g_q/g_k/g_v, [B,H,T,P],
//         stored tf32-rounded). MODE 1: A = g_y, W = Wo, C = d_out plain f32.
// ---------------------------------------------------------------------------
#define GLDA 36
#define A_TILE_F (256*GLDA)   // 9216 floats per buffer
#define BT_TILE_F 4096        // 128 n x 32 k
#define GEMM_SMEM_BYTES ((2*A_TILE_F + 2*BT_TILE_F) * 4)   // 106496
#define NKT 32

template <int MODE>
__global__ __launch_bounds__(512, 1)
void gemm_tc(float* __restrict__ outp)
{
    extern __shared__ float sm_g[];
    const int m0 = blockIdx.y * 256;
    const int n0 = blockIdx.x * 128;
    const int z  = (MODE == 0) ? blockIdx.z : 3;

    const float* Ap = (MODE == 0) ? g_xr : g_y;     // device-side symbol use
    const float* W = g_wr + (size_t)z * 1048576;
    float* Cq = nullptr;
    if (MODE == 0) Cq = (z == 0) ? g_q : ((z == 1) ? g_k : g_v);

    const int tid  = threadIdx.x;
    const int lane = tid & 31;
    const int warp = tid >> 5;
    const int wm = (warp >> 2) * 64;
    const int wn = (warp & 3) * 32;
    const int gid = lane >> 2;
    const int tig = lane & 3;

    const int aRow    = (lane < 16) ? lane : (lane - 16);
    const int aColOff = (lane < 16) ? 0 : 4;

    // B-fragment per-lane relative offsets (bytes, within Bt tile)
    const int rowRel = ((lane >> 4) << 3) + (lane & 7);
    const uint32_t hb = (lane >> 3) & 1;
    uint32_t bOff[2];
#pragma unroll
    for (int nfp = 0; nfp < 2; nfp++) {
        int row = wn + nfp * 16 + rowRel;
        bOff[nfp] = (uint32_t)(row * 128 + 16 * (row & 7)) ^ (hb << 4);
    }

    const uint32_t smBase = smem_u32(sm_g);
    const uint32_t AsB[2] = { smBase, smBase + A_TILE_F * 4 };
    const uint32_t BtB[2] = { smBase + 2 * A_TILE_F * 4,
                              smBase + 2 * A_TILE_F * 4 + BT_TILE_F * 4 };

    float acc[4][4][4];
#pragma unroll
    for (int mf = 0; mf < 4; mf++)
#pragma unroll
        for (int nf = 0; nf < 4; nf++)
#pragma unroll
            for (int i = 0; i < 4; i++) acc[mf][nf][i] = 0.f;

    auto cpA = [&](int kt, int buf) {
#pragma unroll
        for (int r = 0; r < 4; r++) {
            int lin  = tid + r * 512;
            int arow = lin >> 3;
            int ac4  = (lin & 7) * 4;
            cp16(AsB[buf] + (uint32_t)(arow * GLDA + ac4) * 4u,
                 Ap + (size_t)(m0 + arow) * 1024 + kt * 32 + ac4);
        }
    };
    auto ldgB = [&](int kt, float bv[2][4]) {
#pragma unroll
        for (int r = 0; r < 2; r++) {
            int u  = tid + r * 512;
            int kb = u >> 7;
            int n  = u & 127;
            const float* src = W + (size_t)(kt * 32 + kb * 4) * 1024 + n0 + n;
#pragma unroll
            for (int i = 0; i < 4; i++) bv[r][i] = src[(size_t)i * 1024];
        }
    };
    auto stsB = [&](int buf, float bv[2][4]) {
#pragma unroll
        for (int r = 0; r < 2; r++) {
            int u  = tid + r * 512;
            int kb = u >> 7;
            int n  = u & 127;
            uint32_t dst = BtB[buf] + (uint32_t)(n * 128 + 16 * (kb ^ (n & 7)));
            sts128(dst, bv[r][0], bv[r][1], bv[r][2], bv[r][3]);
        }
    };

    {
        float bv[2][4];
        cpA(0, 0);
        cp_commit();
        ldgB(0, bv);
        cp_wait0();
        stsB(0, bv);
    }
    __syncthreads();

    int buf = 0;
    for (int kt = 0; kt < NKT; kt++) {
        float bv[2][4];
        const bool more = (kt + 1 < NKT);
        if (more) {
            ldgB(kt + 1, bv);
            cpA(kt + 1, buf ^ 1);
            cp_commit();
        }

        // ---- compute on buf ----
        const uint32_t aB = AsB[buf] + (uint32_t)((wm + aRow) * GLDA + aColOff) * 4u;
        const uint32_t btb = BtB[buf];
#pragma unroll
        for (int kf = 0; kf < 4; kf++) {
            uint32_t a[4][4];
#pragma unroll
            for (int mf = 0; mf < 4; mf++)
                ldsm4(a[mf][0], a[mf][1], a[mf][2], a[mf][3],
                      aB + (uint32_t)(mf * 16 * GLDA + kf * 8) * 4u);
            uint32_t b[4][2];
            ldsm4(b[0][0], b[0][1], b[1][0], b[1][1], btb + (bOff[0] ^ (kf << 5)));
            ldsm4(b[2][0], b[2][1], b[3][0], b[3][1], btb + (bOff[1] ^ (kf << 5)));
#pragma unroll
            for (int mf = 0; mf < 4; mf++)
#pragma unroll
                for (int nf = 0; nf < 4; nf++)
                    mma_tf32(acc[mf][nf], a[mf], b[nf][0], b[nf][1]);
        }

        if (more) {
            stsB(buf ^ 1, bv);
            cp_wait0();
        }
        __syncthreads();
        buf ^= 1;
    }

    // Epilogue
#pragma unroll
    for (int mf = 0; mf < 4; mf++) {
#pragma unroll
        for (int nf = 0; nf < 4; nf++) {
            int row = m0 + wm + mf * 16 + gid;
            int col = n0 + wn + nf * 8 + tig * 2;
#pragma unroll
            for (int half = 0; half < 2; half++) {
                int rr = row + half * 8;
                float v0 = acc[mf][nf][half * 2];
                float v1 = acc[mf][nf][half * 2 + 1];
                if (MODE == 0) {
                    int b = rr >> 11;
                    int t = rr & 2047;
                    int h = col >> 6;
                    int p = col & 63;
                    *(float2*)&Cq[(((size_t)(b * H_ + h) * T_ + t) * P_ + p)] =
                        make_float2(f2tf32f(v0), f2tf32f(v1));
                } else {
                    *(float2*)&outp[(size_t)rr * 1024 + col] = make_float2(v0, v1);
                }
            }
        }
    }
}

// ---------------------------------------------------------------------------
// tf32 tensor-core flash attention, causal. 256 thr = 8 warps, 128 q-rows,
// kv tiles of 64. K b-frags via direct ldmatrix (natural [kv][d] layout);
// V stored transposed+swizzled in smem, ldmatrix b-frags. Q/K via cp.async.
// ---------------------------------------------------------------------------
#define LDQ 68
#define LDK 68
#define LDP 68
#define KS_OFF (128*LDQ)              // 8704
#define PS_OFF (KS_OFF + 64*LDK)      // 13056
#define VT_OFF (PS_OFF + 128*LDP)     // 21760 (x4 bytes: 87040, 256B-aligned)
#define ATTN_SMEM_FLOATS (VT_OFF + 64*64)
#define ATTN_SMEM_BYTES  (ATTN_SMEM_FLOATS*4)

__global__ __launch_bounds__(256, 1)
void attn_tc()
{
    extern __shared__ float sm[];

    const int bh = blockIdx.y;
    const int b  = bh >> 4;
    const int h  = bh & 15;
    const int qt = (int)gridDim.x - 1 - (int)blockIdx.x;  // heavy blocks first
    const int q0 = qt * 128;

    const size_t base = (size_t)bh * T_ * P_;
    const float* Qp = g_q + base;
    const float* Kp = g_k + base;
    const float* Vp = g_v + base;

    const int tid  = threadIdx.x;
    const int lane = tid & 31;
    const int warp = tid >> 5;
    const int gid  = lane >> 2;
    const int tig  = lane & 3;
    const int aRow    = (lane < 16) ? lane : (lane - 16);
    const int aColOff = (lane < 16) ? 0 : 4;

    const uint32_t smBase = smem_u32(sm);
    const uint32_t QsB = smBase;
    const uint32_t KsB = smBase + KS_OFF * 4;
    const uint32_t PsB = smBase + PS_OFF * 4;
    const uint32_t VtB = smBase + VT_OFF * 4;

    // b-fragment lane constants
    const int rowRel = ((lane >> 4) << 3) + (lane & 7);
    const uint32_t hb = (lane >> 3) & 1;
    uint32_t bK[4], bV[4];
#pragma unroll
    for (int nfp = 0; nfp < 4; nfp++) {
        int row = nfp * 16 + rowRel;
        bK[nfp] = KsB + (uint32_t)(row * LDK + (int)hb * 4) * 4u;
        bV[nfp] = (uint32_t)(row * 256 + 16 * (row & 7)) ^ (hb << 4);
    }

    // Load Q tile (128x64) via cp.async (pre-rounded tf32)
#pragma unroll
    for (int r = 0; r < 8; r++) {
        int it = tid + r * 256;
        int rw = it >> 4;
        int c4 = (it & 15) * 4;
        cp16(QsB + (uint32_t)(rw * LDQ + c4) * 4u,
             Qp + (size_t)(q0 + rw) * 64 + c4);
    }
    cp_commit();

    float accO[8][4];
#pragma unroll
    for (int nf = 0; nf < 8; nf++)
#pragma unroll
        for (int i = 0; i < 4; i++) accO[nf][i] = 0.f;
    float mr0 = -INFINITY, mr1 = -INFINITY, l0 = 0.f, l1 = 0.f;

    const float sc = 0.18033688011112042f;   // 0.125 * log2(e)
    const int ntiles = 2 * qt + 2;

    for (int jt = 0; jt < ntiles; jt++) {
        const int j0 = jt * 64;
        __syncthreads();   // prior compute done with Ks/Vt
        // K via cp.async
#pragma unroll
        for (int r = 0; r < 4; r++) {
            int it = tid + r * 256;
            int rw = it >> 4;
            int c4 = (it & 15) * 4;
            cp16(KsB + (uint32_t)(rw * LDK + c4) * 4u,
                 Kp + (size_t)(j0 + rw) * 64 + c4);
        }
        cp_commit();
        // V: column loads -> swizzled transposed STS.128
#pragma unroll
        for (int r = 0; r < 4; r++) {
            int u   = tid + r * 256;
            int kvb = u >> 6;
            int d   = u & 63;
            const float* src = Vp + (size_t)(j0 + kvb * 4) * 64 + d;
            float v0 = src[0], v1 = src[64], v2 = src[128], v3 = src[192];
            sts128(VtB + (uint32_t)(d * 256 + 16 * (kvb ^ (d & 7))),
                   v0, v1, v2, v3);
        }
        cp_wait0();
        __syncthreads();

        // ---- S = Q K^T  (warp: 16 rows x 64 cols) ----
        float c[8][4];
#pragma unroll
        for (int nf = 0; nf < 8; nf++)
#pragma unroll
            for (int i = 0; i < 4; i++) c[nf][i] = 0.f;

        const uint32_t aBaseQ = QsB + (uint32_t)((warp * 16 + aRow) * LDQ + aColOff) * 4u;
#pragma unroll
        for (int kf = 0; kf < 8; kf++) {
            uint32_t a[4];
            ldsm4(a[0], a[1], a[2], a[3], aBaseQ + (uint32_t)(kf * 8) * 4u);
#pragma unroll
            for (int nfp = 0; nfp < 4; nfp++) {
                uint32_t b0, b1, b2, b3;
                ldsm4(b0, b1, b2, b3, bK[nfp] + (uint32_t)(kf * 32));
                mma_tf32(c[2 * nfp],     a, b0, b1);
                mma_tf32(c[2 * nfp + 1], a, b2, b3);
            }
        }

        // ---- causal mask (last two tiles only) ----
        if (jt >= 2 * qt) {
            int row0 = q0 + warp * 16 + gid;
#pragma unroll
            for (int nf = 0; nf < 8; nf++) {
                int col = j0 + nf * 8 + tig * 2;
                if (col     > row0)     c[nf][0] = -INFINITY;
                if (col + 1 > row0)     c[nf][1] = -INFINITY;
                if (col     > row0 + 8) c[nf][2] = -INFINITY;
                if (col + 1 > row0 + 8) c[nf][3] = -INFINITY;
            }
        }

        // ---- online softmax ----
        float rm0 = -INFINITY, rm1 = -INFINITY;
#pragma unroll
        for (int nf = 0; nf < 8; nf++) {
            rm0 = fmaxf(rm0, fmaxf(c[nf][0], c[nf][1]));
            rm1 = fmaxf(rm1, fmaxf(c[nf][2], c[nf][3]));
        }
#pragma unroll
        for (int off = 1; off < 4; off <<= 1) {
            rm0 = fmaxf(rm0, __shfl_xor_sync(0xffffffffu, rm0, off));
            rm1 = fmaxf(rm1, __shfl_xor_sync(0xffffffffu, rm1, off));
        }
        float mn0 = fmaxf(mr0, rm0);
        float mn1 = fmaxf(mr1, rm1);
        float al0 = exp2f((mr0 - mn0) * sc);
        float al1 = exp2f((mr1 - mn1) * sc);
        float rs0 = 0.f, rs1 = 0.f;
#pragma unroll
        for (int nf = 0; nf < 8; nf++) {
            c[nf][0] = exp2f((c[nf][0] - mn0) * sc);
            c[nf][1] = exp2f((c[nf][1] - mn0) * sc);
            c[nf][2] = exp2f((c[nf][2] - mn1) * sc);
            c[nf][3] = exp2f((c[nf][3] - mn1) * sc);
            rs0 += c[nf][0] + c[nf][1];
            rs1 += c[nf][2] + c[nf][3];
        }
#pragma unroll
        for (int off = 1; off < 4; off <<= 1) {
            rs0 += __shfl_xor_sync(0xffffffffu, rs0, off);
            rs1 += __shfl_xor_sync(0xffffffffu, rs1, off);
        }
        l0 = l0 * al0 + rs0;
        l1 = l1 * al1 + rs1;
        mr0 = mn0;
        mr1 = mn1;
#pragma unroll
        for (int nf = 0; nf < 8; nf++) {
            accO[nf][0] *= al0;
            accO[nf][1] *= al0;
            accO[nf][2] *= al1;
            accO[nf][3] *= al1;
        }

        // ---- stage P (warp-local rows -> only __syncwarp) ----
        {
            float* Ps = sm + PS_OFF;
            float* p0 = Ps + (warp * 16 + gid) * LDP + tig * 2;
            float* p1 = p0 + 8 * LDP;
#pragma unroll
            for (int nf = 0; nf < 8; nf++) {
                ((uint32_t*)p0)[nf * 8]     = f2tf32(c[nf][0]);
                ((uint32_t*)p0)[nf * 8 + 1] = f2tf32(c[nf][1]);
                ((uint32_t*)p1)[nf * 8]     = f2tf32(c[nf][2]);
                ((uint32_t*)p1)[nf * 8 + 1] = f2tf32(c[nf][3]);
            }
        }
        __syncwarp();

        // ---- O += P @ V (V^T in smem, ldmatrix b-frags) ----
        const uint32_t aBaseP = PsB + (uint32_t)((warp * 16 + aRow) * LDP + aColOff) * 4u;
#pragma unroll
        for (int kf = 0; kf < 8; kf++) {
            uint32_t a[4];
            ldsm4(a[0], a[1], a[2], a[3], aBaseP + (uint32_t)(kf * 8) * 4u);
#pragma unroll
            for (int nfp = 0; nfp < 4; nfp++) {
                uint32_t b0, b1, b2, b3;
                ldsm4(b0, b1, b2, b3, VtB + (bV[nfp] ^ (uint32_t)(kf << 5)));
                mma_tf32(accO[2 * nfp],     a, b0, b1);
                mma_tf32(accO[2 * nfp + 1], a, b2, b3);
            }
        }
        __syncwarp();
    }

    // ---- finalize; write tf32-rounded to g_y [B,T,H*P] ----
    float inv0 = 1.f / l0;
    float inv1 = 1.f / l1;
    int rowg = q0 + warp * 16 + gid;
    float* y0 = g_y + ((size_t)(b * T_ + rowg)) * D_ + h * 64 + tig * 2;
    float* y1 = y0 + 8 * (size_t)D_;
#pragma unroll
    for (int nf = 0; nf < 8; nf++) {
        *(float2*)&y0[nf * 8] = make_float2(f2tf32f(accO[nf][0] * inv0),
                                            f2tf32f(accO[nf][1] * inv0));
        *(float2*)&y1[nf * 8] = make_float2(f2tf32f(accO[nf][2] * inv1),
                                            f2tf32f(accO[nf][3] * inv1));
    }
}

// ---------------------------------------------------------------------------
extern "C" void kernel_launch(void* const* d_in, const int* in_sizes, int n_in,
                              void* d_out, int out_size)
{
    const float* x  = (const float*)d_in[0];
    const float* Wq = (const float*)d_in[2];
    const float* Wk = (const float*)d_in[3];
    const float* Wv = (const float*)d_in[4];
    const float* Wo = (const float*)d_in[5];
    float* out = (float*)d_out;

    cudaFuncSetAttribute(gemm_tc<0>, cudaFuncAttributeMaxDynamicSharedMemorySize,
                         GEMM_SMEM_BYTES);
    cudaFuncSetAttribute(gemm_tc<1>, cudaFuncAttributeMaxDynamicSharedMemorySize,
                         GEMM_SMEM_BYTES);
    cudaFuncSetAttribute(attn_tc, cudaFuncAttributeMaxDynamicSharedMemorySize,
                         ATTN_SMEM_BYTES);

    // Round x + weights to tf32 once (3145728 float4s)
    prep_round<<<12288, 256>>>(x, Wq, Wk, Wv, Wo);

    // QKV projections (A/W selected in-kernel; no device-symbol args!)
    gemm_tc<0><<<dim3(8, 32, 3), 512, GEMM_SMEM_BYTES>>>(nullptr);

    // Flash attention
    attn_tc<<<dim3(T_/128, B_*H_), 256, ATTN_SMEM_BYTES>>>();

    // Output projection
    gemm_tc<1><<<dim3(8, 32, 1), 512, GEMM_SMEM_BYTES>>>(out);
}